// round 1
// baseline (speedup 1.0000x reference)
#include <cuda_runtime.h>

#define NP  400000
#define CH  32
#define KK  27
#define TPB 384
#define WPB (TPB/32)

// scratch (allocation-free rule: __device__ globals)
__device__ float g_buf1[(size_t)NP*CH];
__device__ float g_buf2[(size_t)NP*CH];
__device__ float g_stats[128];   // [0:32) sum1 [32:64) sumsq1 [64:96) sum2 [96:128) sumsq2

// ---- packed fp32x2 FMA (Blackwell FFMA2; PTX-only) ----
__device__ __forceinline__ void ffma2(unsigned long long &d, unsigned long long a, unsigned long long b){
    asm("fma.rn.f32x2 %0, %1, %2, %0;" : "+l"(d) : "l"(a), "l"(b));
}
__device__ __forceinline__ unsigned long long pack2(float x){
    unsigned long long r; unsigned u = __float_as_uint(x);
    asm("mov.b64 %0, {%1, %1};" : "=l"(r) : "r"(u));
    return r;
}

// ---- sparse conv: out[n,c] = sum_k sum_i feats[nbr[n,k],i]*mask[n,k]*W[k,i,c] ----
// thread = point; warp cooperatively stages 32 gathered rows into SMEM (coalesced,
// XOR-swizzled); W broadcast from SMEM; 16 f32x2 accumulators per thread.
__global__ void __launch_bounds__(TPB, 1) conv_kernel(
    const float* __restrict__ feats, const float* __restrict__ W,
    const int* __restrict__ nbr, const int* __restrict__ mask,
    float* __restrict__ out)
{
    extern __shared__ float sm[];
    float* Wsh = sm;                         // KK*CH*CH floats = 27648
    float* Fsh = Wsh + KK*CH*CH;             // WPB * 32*32
    int*   Ish = (int*)(Fsh + WPB*CH*CH);    // WPB * 32*KK (mask folded: -1 = inactive)

    const int tid  = threadIdx.x;
    const int warp = tid >> 5, lane = tid & 31;

    // cooperative W load (vectorized)
    {
        const float4* Wg = (const float4*)W;
        float4* Ws = (float4*)Wsh;
        #pragma unroll 1
        for (int i = tid; i < KK*CH*CH/4; i += TPB) Ws[i] = Wg[i];
    }

    // cooperative, coalesced idx+mask load for this warp's 32 points
    {
        long long base = ((long long)blockIdx.x*TPB + warp*32) * KK;
        int* iw = Ish + warp*(32*KK);
        #pragma unroll 1
        for (int j = lane; j < 32*KK; j += 32){
            long long g = base + j;
            int v = -1;
            if (g < (long long)NP*KK){
                int m  = mask[g];
                int id = nbr[g];
                v = m ? id : -1;
            }
            iw[j] = v;
        }
    }
    __syncthreads();

    const int  n     = blockIdx.x*TPB + tid;
    const bool valid = (n < NP);
    float* fw = Fsh + warp*(CH*CH);
    const int* iw = Ish + warp*(32*KK);

    unsigned long long acc[16];
    #pragma unroll
    for (int m = 0; m < 16; m++) acc[m] = 0ull;

    #pragma unroll 1
    for (int k = 0; k < KK; k++){
        // gather phase: warp loads 32 feature rows coalesced (1 line / row),
        // stores XOR-swizzled so compute-phase reads are bank-conflict-free
        #pragma unroll
        for (int r = 0; r < 32; r++){
            int ir = iw[r*KK + k];              // broadcast LDS
            float v = 0.f;
            if (ir >= 0) v = __ldg(feats + ir*CH + lane);   // coalesced 128B row
            fw[r*CH + (lane ^ r)] = v;
        }
        __syncwarp();
        // compute phase: 32x32 FMA per point via 512 f32x2 per warp-instr stream
        const unsigned long long* Wk = (const unsigned long long*)(Wsh + k*CH*CH);
        #pragma unroll
        for (int i = 0; i < CH; i++){
            float fi = fw[lane*CH + (i ^ lane)];            // conflict-free (bank = i^lane)
            unsigned long long fa = pack2(fi);
            const ulonglong2* wr = (const ulonglong2*)(Wk + i*16);  // broadcast LDS.128
            #pragma unroll
            for (int c4 = 0; c4 < 8; c4++){
                ulonglong2 w2 = wr[c4];
                ffma2(acc[2*c4],   fa, w2.x);
                ffma2(acc[2*c4+1], fa, w2.y);
            }
        }
        __syncwarp();
    }

    if (valid){
        float* o = out + (long long)n*CH;
        #pragma unroll
        for (int m = 0; m < 16; m++){
            ((float2*)o)[m] = make_float2(
                __uint_as_float((unsigned)(acc[m] & 0xffffffffu)),
                __uint_as_float((unsigned)(acc[m] >> 32)));
        }
    }
}

// ---- per-channel sum / sumsq reduction (training-mode BN stats) ----
__global__ void reduce_kernel(const float* __restrict__ x, int stats_off)
{
    const int lane = threadIdx.x & 31, warp = threadIdx.x >> 5;
    const int wpb  = blockDim.x >> 5;
    long long row  = (long long)blockIdx.x*wpb + warp;
    const long long stride = (long long)gridDim.x*wpb;
    float s = 0.f, q = 0.f;
    for (; row < NP; row += stride){
        float v = x[row*CH + lane];     // lane = channel -> coalesced
        s += v; q += v*v;
    }
    __shared__ float sh[2][8][33];
    sh[0][warp][lane] = s; sh[1][warp][lane] = q;
    __syncthreads();
    if (warp == 0){
        float a = 0.f, b = 0.f;
        #pragma unroll
        for (int w = 0; w < 8; w++){ a += sh[0][w][lane]; b += sh[1][w][lane]; }
        atomicAdd(&g_stats[stats_off + lane],      a);
        atomicAdd(&g_stats[stats_off + 32 + lane], b);
    }
}

__global__ void zero_stats(){ if (threadIdx.x < 128) g_stats[threadIdx.x] = 0.f; }

// ---- BN (+ optional residual) + ReLU, vectorized float4 ----
__global__ void bnrelu_kernel(const float4* __restrict__ x, int stats_off,
    const float* __restrict__ gamma, const float* __restrict__ beta,
    const float4* __restrict__ res, float4* __restrict__ out)
{
    long long i = (long long)blockIdx.x*blockDim.x + threadIdx.x;
    if (i >= (long long)NP*CH/4) return;
    int c0 = (int)(i & 7) * 4;
    const float invN = 1.0f / NP;
    float4 v = x[i];
    float4 r4 = res ? res[i] : make_float4(0.f,0.f,0.f,0.f);
    float4 o;
#define BN_ONE(comp, c) { \
        float mean = g_stats[stats_off + c0 + c] * invN; \
        float var  = g_stats[stats_off + 32 + c0 + c] * invN - mean*mean; \
        float sc   = rsqrtf(var + 1e-5f) * gamma[c0 + c]; \
        float val  = (v.comp - mean)*sc + beta[c0 + c]; \
        if (res) val += r4.comp; \
        o.comp = fmaxf(val, 0.f); }
    BN_ONE(x, 0) BN_ONE(y, 1) BN_ONE(z, 2) BN_ONE(w, 3)
#undef BN_ONE
    out[i] = o;
}

extern "C" void kernel_launch(void* const* d_in, const int* in_sizes, int n_in,
                              void* d_out, int out_size)
{
    const float* feats  = (const float*)d_in[0];
    const float* W1     = (const float*)d_in[1];
    const float* gamma1 = (const float*)d_in[2];
    const float* beta1  = (const float*)d_in[3];
    const float* W2     = (const float*)d_in[4];
    const float* gamma2 = (const float*)d_in[5];
    const float* beta2  = (const float*)d_in[6];
    const int*   nbr    = (const int*)d_in[7];
    const int*   mask   = (const int*)d_in[8];
    float* out = (float*)d_out;

    float *buf1, *buf2;
    cudaGetSymbolAddress((void**)&buf1, g_buf1);
    cudaGetSymbolAddress((void**)&buf2, g_buf2);

    const int smem = (KK*CH*CH + WPB*CH*CH + WPB*32*KK) * 4;   // ~201 KB
    cudaFuncSetAttribute(conv_kernel, cudaFuncAttributeMaxDynamicSharedMemorySize, smem);

    const int gridc = (NP + TPB - 1) / TPB;
    const long long ne4 = (long long)NP*CH/4;
    const int gridb = (int)((ne4 + 255) / 256);

    zero_stats<<<1,128>>>();
    // h = relu(bn1(conv1(feats)))
    conv_kernel<<<gridc, TPB, smem>>>(feats, W1, nbr, mask, buf1);
    reduce_kernel<<<592, 256>>>(buf1, 0);
    bnrelu_kernel<<<gridb, 256>>>((const float4*)buf1, 0, gamma1, beta1, nullptr, (float4*)buf2);
    // out = relu(bn2(conv2(h)) + feats)
    conv_kernel<<<gridc, TPB, smem>>>(buf2, W2, nbr, mask, buf1);
    reduce_kernel<<<592, 256>>>(buf1, 64);
    bnrelu_kernel<<<gridb, 256>>>((const float4*)buf1, 64, gamma2, beta2,
                                  (const float4*)feats, (float4*)out);
}

// round 3
// speedup vs baseline: 1.3457x; 1.3457x over previous
#include <cuda_runtime.h>
#include <cuda_bf16.h>

#define NP   400000
#define CH   32
#define KK   27
#define TPB  384
#define TILE 384
#define NT   ((NP + TILE - 1) / TILE)   // 1042

// ---- device scratch (allocation-free rule) ----
__device__ float g_buf1[(size_t)NP*CH];
__device__ float g_buf2[(size_t)NP*CH];
__device__ float g_stats[128];               // [0:64) conv1 sum/sumsq, [64:128) conv2
__device__ unsigned short g_wt[2][KK*2048];  // per-k 4KB: [Wh 2KB | Wl 2KB], swizzled

// ---- smem layout (bytes) ----
#define SM_W   0                       // 27*4096 = 110592
#define SM_AH  110592                  // 384*64  = 24576
#define SM_AL  (110592+24576+64)       // = 135232 (staggered +64 for STS bank split)
#define SM_IDX (SM_AL+24576)           // = 159808, 384*27*4 = 41472
#define SM_SC  (SM_IDX+41472)          // 64 floats
#define SM_ST  (SM_SC+256)             // 64 floats
#define SM_TOT (SM_ST+256)             // 201792

// ============ helpers ============
__device__ __forceinline__ unsigned smem_u32(const void* p){
    unsigned a; asm("{ .reg .u64 t; cvta.to.shared.u64 t, %1; cvt.u32.u64 %0, t; }"
                    : "=r"(a) : "l"(p));
    return a;
}
__device__ __forceinline__ void ldmx4(unsigned* r, unsigned addr){
    asm volatile("ldmatrix.sync.aligned.m8n8.x4.shared.b16 {%0,%1,%2,%3}, [%4];"
        : "=r"(r[0]),"=r"(r[1]),"=r"(r[2]),"=r"(r[3]) : "r"(addr));
}
__device__ __forceinline__ void ldmx4t(unsigned* r, unsigned addr){
    asm volatile("ldmatrix.sync.aligned.m8n8.x4.trans.shared.b16 {%0,%1,%2,%3}, [%4];"
        : "=r"(r[0]),"=r"(r[1]),"=r"(r[2]),"=r"(r[3]) : "r"(addr));
}
__device__ __forceinline__ void mma16816(float* d, const unsigned* a, const unsigned* b){
    asm volatile("mma.sync.aligned.m16n8k16.row.col.f32.bf16.bf16.f32 "
        "{%0,%1,%2,%3}, {%4,%5,%6,%7}, {%8,%9}, {%0,%1,%2,%3};"
        : "+f"(d[0]),"+f"(d[1]),"+f"(d[2]),"+f"(d[3])
        : "r"(a[0]),"r"(a[1]),"r"(a[2]),"r"(a[3]), "r"(b[0]),"r"(b[1]));
}
__device__ __forceinline__ unsigned pack_bf16(float x, float y){
    return (unsigned)__bfloat16_as_ushort(__float2bfloat16(x)) |
           ((unsigned)__bfloat16_as_ushort(__float2bfloat16(y)) << 16);
}

// ============ W prep: fp32 -> swizzled bf16 hi/lo tiles ============
__global__ void prep_w(const float* __restrict__ W1, const float* __restrict__ W2){
    int idx = blockIdx.x*blockDim.x + threadIdx.x;
    if (idx >= 2*KK*CH*CH) return;
    int w   = idx / (KK*CH*CH);
    int rem = idx % (KK*CH*CH);
    int k = rem / (CH*CH);
    int i = (rem / CH) % CH;   // input channel  (GEMM K)  -> row
    int c = rem % CH;          // output channel (GEMM N)   -> col
    float v = (w ? W2 : W1)[(k*CH + i)*CH + c];
    __nv_bfloat16 h = __float2bfloat16(v);
    __nv_bfloat16 l = __float2bfloat16(v - __bfloat162float(h));
    // row i: 64B = 4 units of 16B, unit u = c>>3 swizzled by (i>>1)&3
    unsigned off = i*64 + ((((unsigned)(c>>3)) ^ ((i>>1)&3)) << 4) + (c&7)*2;
    unsigned short* dst = g_wt[w] + k*2048;
    dst[off>>1]          = __bfloat16_as_ushort(h);
    dst[(off>>1) + 1024] = __bfloat16_as_ushort(l);   // Wl region at +2048B
}

__global__ void zero_stats(){ if (threadIdx.x < 128) g_stats[threadIdx.x] = 0.f; }

// ============ conv via mma.sync: out[n,c] = sum_k sum_i in'[nbr,i] * W[k,i,c] ============
__global__ void __launch_bounds__(TPB,1) conv_mma(
    const float* __restrict__ in, const unsigned short* __restrict__ wt,
    const int* __restrict__ nbr, const int* __restrict__ mask,
    float* __restrict__ out, int stats_off, int bn_in,
    const float* __restrict__ gam, const float* __restrict__ bet)
{
    extern __shared__ char smem[];
    const unsigned sb = smem_u32(smem);
    const int tid = threadIdx.x, w = tid >> 5, lane = tid & 31;
    const int tile = blockIdx.x;

    if (tid < 64) ((float*)(smem + SM_ST))[tid] = 0.f;
    if (bn_in && tid < CH){
        float mean = g_stats[tid] * (1.f/NP);
        float var  = g_stats[32+tid] * (1.f/NP) - mean*mean;
        float sc   = rsqrtf(var + 1e-5f) * gam[tid];
        ((float*)(smem + SM_SC))[tid]      = sc;
        ((float*)(smem + SM_SC))[32 + tid] = bet[tid] - mean*sc;
    }
    // W tiles -> smem (110592B)
    {
        const uint4* s = (const uint4*)wt;
        uint4* d = (uint4*)(smem + SM_W);
        #pragma unroll 1
        for (int i = tid; i < (KK*4096)/16; i += TPB) d[i] = s[i];
    }
    // fold idx+mask for this tile
    {
        long long base = (long long)tile * TILE * KK;
        int* I = (int*)(smem + SM_IDX);
        #pragma unroll 1
        for (int t = tid; t < TILE*KK; t += TPB){
            long long g = base + t;
            int v = -1;
            if (g < (long long)NP*KK && mask[g]) v = nbr[g];
            I[t] = v;
        }
    }
    __syncthreads();

    const int p = lane & 15, half = lane >> 4;
    float sc0 = 1.f, sc1 = 1.f, sh0 = 0.f, sh1 = 0.f;
    if (bn_in){
        const float* S = (const float*)(smem + SM_SC);
        sc0 = S[2*p]; sc1 = S[2*p+1]; sh0 = S[32+2*p]; sh1 = S[32+2*p+1];
    }

    const int RB = w * 32;                      // this warp's 32 rows
    const int* I = (const int*)(smem + SM_IDX);
    const unsigned abase = half ? (sb + SM_AL) : (sb + SM_AH);
    const int lr = lane & 15, lc = lane >> 4;

    float acc[2][4][4];
    #pragma unroll
    for (int a = 0; a < 2; a++)
        #pragma unroll
        for (int b = 0; b < 4; b++)
            #pragma unroll
            for (int c = 0; c < 4; c++) acc[a][b][c] = 0.f;

    #pragma unroll 1
    for (int k = 0; k < KK; k++){
        // ---- gather 32 rows (own region only; no CTA sync needed) ----
        #pragma unroll 1
        for (int jo = 0; jo < 32; jo += 8){
            int ir[8]; float2 v[8];
            #pragma unroll
            for (int j = 0; j < 8; j++) ir[j] = I[(RB + jo + j)*KK + k];
            #pragma unroll
            for (int j = 0; j < 8; j++){
                float2 t = make_float2(0.f, 0.f);
                if (ir[j] >= 0) t = *(const float2*)(in + (size_t)ir[j]*CH + 2*p);
                v[j] = t;
            }
            #pragma unroll
            for (int j = 0; j < 8; j++){
                float x = v[j].x, y = v[j].y;
                if (bn_in && ir[j] >= 0){
                    x = fmaxf(x*sc0 + sh0, 0.f);
                    y = fmaxf(y*sc1 + sh1, 0.f);
                }
                unsigned word;
                if (half == 0){
                    word = pack_bf16(x, y);                       // hi
                } else {
                    float rx = x - __bfloat162float(__float2bfloat16(x));
                    float ry = y - __bfloat162float(__float2bfloat16(y));
                    word = pack_bf16(rx, ry);                     // lo (residual)
                }
                int row = RB + jo + j;
                unsigned off = row*64 + ((((unsigned)(p>>2)) ^ ((row>>1)&3)) << 4) + (p&3)*4;
                asm volatile("st.shared.u32 [%0], %1;" :: "r"(abase + off), "r"(word));
            }
        }
        __syncwarp();

        // ---- A fragments (hi + lo), canonical ldmatrix pattern ----
        unsigned ah[2][2][4], al[2][2][4];
        #pragma unroll
        for (int rb = 0; rb < 2; rb++)
            #pragma unroll
            for (int kb = 0; kb < 2; kb++){
                int row = RB + rb*16 + lr;
                unsigned u  = kb*2 + lc;
                unsigned sw = ((u ^ ((row>>1)&3)) << 4);
                ldmx4(ah[rb][kb], sb + SM_AH + row*64 + sw);
                ldmx4(al[rb][kb], sb + SM_AL + row*64 + sw);
            }

        // ---- B fragments + 48 mma ----
        const unsigned wk = sb + SM_W + k*4096;
        #pragma unroll
        for (int nq = 0; nq < 4; nq++){
            unsigned bh[4], bl[4];
            unsigned sw = ((((unsigned)nq) ^ ((lane>>1)&3)) << 4);
            ldmx4t(bh, wk +        lane*64 + sw);
            ldmx4t(bl, wk + 2048 + lane*64 + sw);
            #pragma unroll
            for (int rb = 0; rb < 2; rb++){
                mma16816(acc[rb][nq], ah[rb][0], bh + 0);
                mma16816(acc[rb][nq], ah[rb][1], bh + 2);
                mma16816(acc[rb][nq], al[rb][0], bh + 0);
                mma16816(acc[rb][nq], al[rb][1], bh + 2);
                mma16816(acc[rb][nq], ah[rb][0], bl + 0);
                mma16816(acc[rb][nq], ah[rb][1], bl + 2);
            }
        }
        __syncwarp();
    }

    // ---- epilogue: store raw conv output + fused BN stats ----
    float s[8], q[8];
    #pragma unroll
    for (int i = 0; i < 8; i++){ s[i] = 0.f; q[i] = 0.f; }

    const int r0 = tile*TILE + RB + (lane >> 2);
    const int cc = (lane & 3)*2;
    #pragma unroll
    for (int rb = 0; rb < 2; rb++){
        #pragma unroll
        for (int nq = 0; nq < 4; nq++){
            float a0 = acc[rb][nq][0], a1 = acc[rb][nq][1];
            float a2 = acc[rb][nq][2], a3 = acc[rb][nq][3];
            int m0 = r0 + rb*16, m1 = m0 + 8;
            int c  = nq*8 + cc;
            if (m0 < NP) *(float2*)(out + (size_t)m0*CH + c) = make_float2(a0, a1);
            if (m1 < NP) *(float2*)(out + (size_t)m1*CH + c) = make_float2(a2, a3);
            s[nq*2+0] += a0 + a2;  q[nq*2+0] += a0*a0 + a2*a2;
            s[nq*2+1] += a1 + a3;  q[nq*2+1] += a1*a1 + a3*a3;
        }
    }
    #pragma unroll
    for (int i = 0; i < 8; i++){
        #pragma unroll
        for (int off = 4; off < 32; off <<= 1){
            s[i] += __shfl_xor_sync(0xffffffffu, s[i], off);
            q[i] += __shfl_xor_sync(0xffffffffu, q[i], off);
        }
    }
    if (lane < 4){
        float* st = (float*)(smem + SM_ST);
        #pragma unroll
        for (int nq = 0; nq < 4; nq++){
            atomicAdd(&st[     nq*8 + lane*2    ], s[nq*2+0]);
            atomicAdd(&st[     nq*8 + lane*2 + 1], s[nq*2+1]);
            atomicAdd(&st[32 + nq*8 + lane*2    ], q[nq*2+0]);
            atomicAdd(&st[32 + nq*8 + lane*2 + 1], q[nq*2+1]);
        }
    }
    __syncthreads();
    if (tid < 64) atomicAdd(&g_stats[stats_off + tid], ((float*)(smem + SM_ST))[tid]);
}

// ---- final BN + residual + ReLU ----
__global__ void bnrelu_kernel(const float4* __restrict__ x, int stats_off,
    const float* __restrict__ gamma, const float* __restrict__ beta,
    const float4* __restrict__ res, float4* __restrict__ out)
{
    long long i = (long long)blockIdx.x*blockDim.x + threadIdx.x;
    if (i >= (long long)NP*CH/4) return;
    int c0 = (int)(i & 7) * 4;
    const float invN = 1.0f / NP;
    float4 v = x[i];
    float4 r4 = res ? res[i] : make_float4(0.f,0.f,0.f,0.f);
    float4 o;
#define BN_ONE(comp, c) { \
        float mean = g_stats[stats_off + c0 + c] * invN; \
        float var  = g_stats[stats_off + 32 + c0 + c] * invN - mean*mean; \
        float sc   = rsqrtf(var + 1e-5f) * gamma[c0 + c]; \
        float val  = (v.comp - mean)*sc + beta[c0 + c]; \
        if (res) val += r4.comp; \
        o.comp = fmaxf(val, 0.f); }
    BN_ONE(x, 0) BN_ONE(y, 1) BN_ONE(z, 2) BN_ONE(w, 3)
#undef BN_ONE
    out[i] = o;
}

extern "C" void kernel_launch(void* const* d_in, const int* in_sizes, int n_in,
                              void* d_out, int out_size)
{
    const float* feats  = (const float*)d_in[0];
    const float* W1     = (const float*)d_in[1];
    const float* gamma1 = (const float*)d_in[2];
    const float* beta1  = (const float*)d_in[3];
    const float* W2     = (const float*)d_in[4];
    const float* gamma2 = (const float*)d_in[5];
    const float* beta2  = (const float*)d_in[6];
    const int*   nbr    = (const int*)d_in[7];
    const int*   mask   = (const int*)d_in[8];
    float* out = (float*)d_out;

    float *buf1, *buf2; unsigned short* wt;
    cudaGetSymbolAddress((void**)&buf1, g_buf1);
    cudaGetSymbolAddress((void**)&buf2, g_buf2);
    cudaGetSymbolAddress((void**)&wt,   g_wt);

    cudaFuncSetAttribute(conv_mma, cudaFuncAttributeMaxDynamicSharedMemorySize, SM_TOT);

    const long long ne4 = (long long)NP*CH/4;
    const int gridb = (int)((ne4 + 255) / 256);

    zero_stats<<<1,128>>>();
    prep_w<<<(2*KK*CH*CH + 255)/256, 256>>>(W1, W2);
    // conv1: raw -> buf1, stats@0
    conv_mma<<<NT, TPB, SM_TOT>>>(feats, wt, nbr, mask, buf1,
                                  0, 0, (const float*)0, (const float*)0);
    // conv2: gather applies BN1(stats@0)+ReLU; raw -> buf2, stats@64
    conv_mma<<<NT, TPB, SM_TOT>>>(buf1, wt + KK*2048, nbr, mask, buf2,
                                  64, 1, gamma1, beta1);
    // out = relu(BN2(buf2) + feats)
    bnrelu_kernel<<<gridb, 256>>>((const float4*)buf2, 64, gamma2, beta2,
                                  (const float4*)feats, (float4*)out);
}

// round 4
// speedup vs baseline: 2.5638x; 1.9052x over previous
#include <cuda_runtime.h>
#include <cuda_bf16.h>

#define NP   400000
#define CH   32
#define KK   27
#define TPB  384
#define TILE 384
#define NT   ((NP + TILE - 1) / TILE)   // 1042

// ---- device scratch (allocation-free rule) ----
__device__ float g_buf1[(size_t)NP*CH];
__device__ float g_buf2[(size_t)NP*CH];
__device__ float g_stats[128];               // [0:64) conv1 sum/sumsq, [64:128) conv2
__device__ unsigned short g_wt[2][KK*2048];  // per-k 4KB: [Wh 2KB | Wl 2KB], swizzled

// ---- smem layout (bytes) ----
#define IDXS   385                      // idx row stride (bank-conflict-free)
#define SM_W   0                        // 27*4096 = 110592
#define SM_IDX 110592                   // 27*385*4 = 41580 -> pad 41600
#define SM_SC  (110592+41600)           // 64 floats
#define SM_ST  (SM_SC+256)              // 64 floats
#define SM_TOT (SM_ST+256)              // 152704

// ============ helpers ============
__device__ __forceinline__ unsigned smem_u32(const void* p){
    unsigned a; asm("{ .reg .u64 t; cvta.to.shared.u64 t, %1; cvt.u32.u64 %0, t; }"
                    : "=r"(a) : "l"(p));
    return a;
}
__device__ __forceinline__ void ldmx4t(unsigned* r, unsigned addr){
    asm volatile("ldmatrix.sync.aligned.m8n8.x4.trans.shared.b16 {%0,%1,%2,%3}, [%4];"
        : "=r"(r[0]),"=r"(r[1]),"=r"(r[2]),"=r"(r[3]) : "r"(addr));
}
__device__ __forceinline__ void mma16816(float* d, const unsigned* a, const unsigned* b){
    asm volatile("mma.sync.aligned.m16n8k16.row.col.f32.bf16.bf16.f32 "
        "{%0,%1,%2,%3}, {%4,%5,%6,%7}, {%8,%9}, {%0,%1,%2,%3};"
        : "+f"(d[0]),"+f"(d[1]),"+f"(d[2]),"+f"(d[3])
        : "r"(a[0]),"r"(a[1]),"r"(a[2]),"r"(a[3]), "r"(b[0]),"r"(b[1]));
}
__device__ __forceinline__ unsigned pack_bf16(float x, float y){
    return (unsigned)__bfloat16_as_ushort(__float2bfloat16(x)) |
           ((unsigned)__bfloat16_as_ushort(__float2bfloat16(y)) << 16);
}

// ============ W prep: fp32 -> swizzled bf16 hi/lo tiles (B operand) ============
__global__ void prep_w(const float* __restrict__ W1, const float* __restrict__ W2){
    int idx = blockIdx.x*blockDim.x + threadIdx.x;
    if (idx >= 2*KK*CH*CH) return;
    int w   = idx / (KK*CH*CH);
    int rem = idx % (KK*CH*CH);
    int k = rem / (CH*CH);
    int i = (rem / CH) % CH;   // input channel  (GEMM K)  -> row
    int c = rem % CH;          // output channel (GEMM N)  -> col
    float v = (w ? W2 : W1)[(k*CH + i)*CH + c];
    __nv_bfloat16 h = __float2bfloat16(v);
    __nv_bfloat16 l = __float2bfloat16(v - __bfloat162float(h));
    unsigned off = i*64 + ((((unsigned)(c>>3)) ^ ((i>>1)&3)) << 4) + (c&7)*2;
    unsigned short* dst = g_wt[w] + k*2048;
    dst[off>>1]          = __bfloat16_as_ushort(h);
    dst[(off>>1) + 1024] = __bfloat16_as_ushort(l);
}

__global__ void zero_stats(){ if (threadIdx.x < 128) g_stats[threadIdx.x] = 0.f; }

// ============ conv via mma.sync, register-direct A fragments ============
__global__ void __launch_bounds__(TPB,1) conv_mma(
    const float* __restrict__ in, const unsigned short* __restrict__ wt,
    const int* __restrict__ nbr, const int* __restrict__ mask,
    float* __restrict__ out, int stats_off, int bn_in,
    const float* __restrict__ gam, const float* __restrict__ bet)
{
    extern __shared__ char smem[];
    const unsigned sb = smem_u32(smem);
    const int tid = threadIdx.x, w = tid >> 5, lane = tid & 31;
    const int tile = blockIdx.x;

    if (tid < 64) ((float*)(smem + SM_ST))[tid] = 0.f;
    if (bn_in && tid < CH){
        float mean = g_stats[tid] * (1.f/NP);
        float var  = g_stats[32+tid] * (1.f/NP) - mean*mean;
        float sc   = rsqrtf(var + 1e-5f) * gam[tid];
        ((float*)(smem + SM_SC))[tid]      = sc;
        ((float*)(smem + SM_SC))[32 + tid] = bet[tid] - mean*sc;
    }
    // W tiles -> smem (110592B), coalesced
    {
        const uint4* s = (const uint4*)wt;
        uint4* d = (uint4*)(smem + SM_W);
        #pragma unroll 1
        for (int i = tid; i < (KK*4096)/16; i += TPB) d[i] = s[i];
    }
    // fold idx+mask -> smem, k-major layout I[k*IDXS + row]
    {
        long long base = (long long)tile * TILE * KK;
        int* I = (int*)(smem + SM_IDX);
        #pragma unroll 1
        for (int t = tid; t < TILE*KK; t += TPB){
            long long g = base + t;
            int vv = -1;
            if (g < (long long)NP*KK && mask[g]) vv = nbr[g];
            int row = t / KK, k = t - row*KK;
            I[k*IDXS + row] = vv;
        }
    }
    __syncthreads();

    // per-thread fragment coordinates
    const int RB = w * 32;
    const int r_lo = lane >> 2;            // row within 8-block
    const int C0   = (lane & 3) * 2;       // first col pair
    const int* I = (const int*)(smem + SM_IDX);

    // BN coefficients for this thread's 4 col-pairs
    float scx[4], scy[4], shx[4], shy[4];
    if (bn_in){
        const float* S = (const float*)(smem + SM_SC);
        #pragma unroll
        for (int ci = 0; ci < 4; ci++){
            int c = C0 + ci*8;
            scx[ci] = S[c];      scy[ci] = S[c+1];
            shx[ci] = S[32+c];   shy[ci] = S[32+c+1];
        }
    }

    float acc[2][4][4];
    #pragma unroll
    for (int a = 0; a < 2; a++)
        #pragma unroll
        for (int b = 0; b < 4; b++)
            #pragma unroll
            for (int c = 0; c < 4; c++) acc[a][b][c] = 0.f;

    // ---- prefetch k=0 ----
    int ir[4]; float2 v[4][4];
    #pragma unroll
    for (int ri = 0; ri < 4; ri++) ir[ri] = I[RB + r_lo + ri*8];
    #pragma unroll
    for (int ri = 0; ri < 4; ri++){
        const float* rp = in + (size_t)ir[ri]*CH;
        #pragma unroll
        for (int ci = 0; ci < 4; ci++){
            float2 t = make_float2(0.f, 0.f);
            if (ir[ri] >= 0) t = *(const float2*)(rp + C0 + ci*8);
            v[ri][ci] = t;
        }
    }

    #pragma unroll 1
    for (int k = 0; k < KK; k++){
        // ---- convert current v -> hi/lo fragment words ----
        unsigned wh[4][4], wl[4][4];
        #pragma unroll
        for (int ri = 0; ri < 4; ri++){
            const bool ok = (ir[ri] >= 0);
            #pragma unroll
            for (int ci = 0; ci < 4; ci++){
                float x = v[ri][ci].x, y = v[ri][ci].y;
                if (bn_in && ok){
                    x = fmaxf(x*scx[ci] + shx[ci], 0.f);
                    y = fmaxf(y*scy[ci] + shy[ci], 0.f);
                }
                float hx = __bfloat162float(__float2bfloat16(x));
                float hy = __bfloat162float(__float2bfloat16(y));
                wh[ri][ci] = pack_bf16(x, y);
                wl[ri][ci] = pack_bf16(x - hx, y - hy);
            }
        }

        // ---- prefetch next k (overlaps with mma below) ----
        if (k + 1 < KK){
            #pragma unroll
            for (int ri = 0; ri < 4; ri++) ir[ri] = I[(k+1)*IDXS + RB + r_lo + ri*8];
            #pragma unroll
            for (int ri = 0; ri < 4; ri++){
                const float* rp = in + (size_t)ir[ri]*CH;
                #pragma unroll
                for (int ci = 0; ci < 4; ci++){
                    float2 t = make_float2(0.f, 0.f);
                    if (ir[ri] >= 0) t = *(const float2*)(rp + C0 + ci*8);
                    v[ri][ci] = t;
                }
            }
        }

        // ---- assemble A fragments (register permute only) ----
        unsigned ah[2][2][4], al[2][2][4];
        #pragma unroll
        for (int rb = 0; rb < 2; rb++)
            #pragma unroll
            for (int kb = 0; kb < 2; kb++){
                ah[rb][kb][0] = wh[rb*2  ][kb*2  ];
                ah[rb][kb][1] = wh[rb*2+1][kb*2  ];
                ah[rb][kb][2] = wh[rb*2  ][kb*2+1];
                ah[rb][kb][3] = wh[rb*2+1][kb*2+1];
                al[rb][kb][0] = wl[rb*2  ][kb*2  ];
                al[rb][kb][1] = wl[rb*2+1][kb*2  ];
                al[rb][kb][2] = wl[rb*2  ][kb*2+1];
                al[rb][kb][3] = wl[rb*2+1][kb*2+1];
            }

        // ---- B fragments from smem + 48 mma ----
        const unsigned wk = sb + SM_W + k*4096;
        #pragma unroll
        for (int nq = 0; nq < 4; nq++){
            unsigned bh[4], bl[4];
            unsigned sw = ((((unsigned)nq) ^ ((lane>>1)&3)) << 4);
            ldmx4t(bh, wk +        lane*64 + sw);
            ldmx4t(bl, wk + 2048 + lane*64 + sw);
            #pragma unroll
            for (int rb = 0; rb < 2; rb++){
                mma16816(acc[rb][nq], ah[rb][0], bh + 0);
                mma16816(acc[rb][nq], ah[rb][1], bh + 2);
                mma16816(acc[rb][nq], al[rb][0], bh + 0);
                mma16816(acc[rb][nq], al[rb][1], bh + 2);
                mma16816(acc[rb][nq], ah[rb][0], bl + 0);
                mma16816(acc[rb][nq], ah[rb][1], bl + 2);
            }
        }
    }

    // ---- epilogue: store raw conv output + fused BN stats ----
    float s[8], q[8];
    #pragma unroll
    for (int i = 0; i < 8; i++){ s[i] = 0.f; q[i] = 0.f; }

    const int r0 = tile*TILE + RB + r_lo;
    #pragma unroll
    for (int rb = 0; rb < 2; rb++){
        #pragma unroll
        for (int nq = 0; nq < 4; nq++){
            float a0 = acc[rb][nq][0], a1 = acc[rb][nq][1];
            float a2 = acc[rb][nq][2], a3 = acc[rb][nq][3];
            int m0 = r0 + rb*16, m1 = m0 + 8;
            int c  = nq*8 + C0;
            if (m0 < NP) *(float2*)(out + (size_t)m0*CH + c) = make_float2(a0, a1);
            if (m1 < NP) *(float2*)(out + (size_t)m1*CH + c) = make_float2(a2, a3);
            s[nq*2+0] += a0 + a2;  q[nq*2+0] += a0*a0 + a2*a2;
            s[nq*2+1] += a1 + a3;  q[nq*2+1] += a1*a1 + a3*a3;
        }
    }
    #pragma unroll
    for (int i = 0; i < 8; i++){
        #pragma unroll
        for (int off = 4; off < 32; off <<= 1){
            s[i] += __shfl_xor_sync(0xffffffffu, s[i], off);
            q[i] += __shfl_xor_sync(0xffffffffu, q[i], off);
        }
    }
    if (lane < 4){
        float* st = (float*)(smem + SM_ST);
        #pragma unroll
        for (int nq = 0; nq < 4; nq++){
            atomicAdd(&st[     nq*8 + lane*2    ], s[nq*2+0]);
            atomicAdd(&st[     nq*8 + lane*2 + 1], s[nq*2+1]);
            atomicAdd(&st[32 + nq*8 + lane*2    ], q[nq*2+0]);
            atomicAdd(&st[32 + nq*8 + lane*2 + 1], q[nq*2+1]);
        }
    }
    __syncthreads();
    if (tid < 64) atomicAdd(&g_stats[stats_off + tid], ((float*)(smem + SM_ST))[tid]);
}

// ---- final BN + residual + ReLU ----
__global__ void bnrelu_kernel(const float4* __restrict__ x, int stats_off,
    const float* __restrict__ gamma, const float* __restrict__ beta,
    const float4* __restrict__ res, float4* __restrict__ out)
{
    long long i = (long long)blockIdx.x*blockDim.x + threadIdx.x;
    if (i >= (long long)NP*CH/4) return;
    int c0 = (int)(i & 7) * 4;
    const float invN = 1.0f / NP;
    float4 v = x[i];
    float4 r4 = res ? res[i] : make_float4(0.f,0.f,0.f,0.f);
    float4 o;
#define BN_ONE(comp, c) { \
        float mean = g_stats[stats_off + c0 + c] * invN; \
        float var  = g_stats[stats_off + 32 + c0 + c] * invN - mean*mean; \
        float sc   = rsqrtf(var + 1e-5f) * gamma[c0 + c]; \
        float val  = (v.comp - mean)*sc + beta[c0 + c]; \
        if (res) val += r4.comp; \
        o.comp = fmaxf(val, 0.f); }
    BN_ONE(x, 0) BN_ONE(y, 1) BN_ONE(z, 2) BN_ONE(w, 3)
#undef BN_ONE
    out[i] = o;
}

extern "C" void kernel_launch(void* const* d_in, const int* in_sizes, int n_in,
                              void* d_out, int out_size)
{
    const float* feats  = (const float*)d_in[0];
    const float* W1     = (const float*)d_in[1];
    const float* gamma1 = (const float*)d_in[2];
    const float* beta1  = (const float*)d_in[3];
    const float* W2     = (const float*)d_in[4];
    const float* gamma2 = (const float*)d_in[5];
    const float* beta2  = (const float*)d_in[6];
    const int*   nbr    = (const int*)d_in[7];
    const int*   mask   = (const int*)d_in[8];
    float* out = (float*)d_out;

    float *buf1, *buf2; unsigned short* wt;
    cudaGetSymbolAddress((void**)&buf1, g_buf1);
    cudaGetSymbolAddress((void**)&buf2, g_buf2);
    cudaGetSymbolAddress((void**)&wt,   g_wt);

    cudaFuncSetAttribute(conv_mma, cudaFuncAttributeMaxDynamicSharedMemorySize, SM_TOT);

    const long long ne4 = (long long)NP*CH/4;
    const int gridb = (int)((ne4 + 255) / 256);

    zero_stats<<<1,128>>>();
    prep_w<<<(2*KK*CH*CH + 255)/256, 256>>>(W1, W2);
    // conv1: raw -> buf1, stats@0
    conv_mma<<<NT, TPB, SM_TOT>>>(feats, wt, nbr, mask, buf1,
                                  0, 0, (const float*)0, (const float*)0);
    // conv2: gather applies BN1(stats@0)+ReLU; raw -> buf2, stats@64
    conv_mma<<<NT, TPB, SM_TOT>>>(buf1, wt + KK*2048, nbr, mask, buf2,
                                  64, 1, gamma1, beta1);
    // out = relu(BN2(buf2) + feats)
    bnrelu_kernel<<<gridb, 256>>>((const float4*)buf2, 64, gamma2, beta2,
                                  (const float4*)feats, (float4*)out);
}

// round 5
// speedup vs baseline: 3.0895x; 1.2051x over previous
#include <cuda_runtime.h>
#include <cuda_bf16.h>

#define NP   400000
#define CH   32
#define KK   27
#define TPB  512
#define TILE 512
#define NT   ((NP + TILE - 1) / TILE)   // 782
#define IDXS 513

// ---- device scratch (allocation-free rule) ----
__device__ float g_buf1[(size_t)NP*CH];
__device__ float g_buf2[(size_t)NP*CH];
__device__ float g_stats[128];                 // [0:64) conv1 sum/sumsq, [64:128) conv2
__device__ unsigned short g_wt[2][KK*2048];    // per-k 4KB: [Wh 2KB | Wl 2KB], swizzled
__device__ unsigned g_pk[(size_t)NP*32];       // packed input: per row 128B = [hi 16w | lo 16w]

// ---- conv smem layout (bytes) ----
#define SM_W   0                        // 27*4096 = 110592
#define SM_IDX 110592                   // 27*513*4 = 55404 -> pad 55424
#define SM_ST  (110592+55424)           // 64 floats
#define SM_TOT (SM_ST+256)              // 166272

// ============ helpers ============
__device__ __forceinline__ unsigned smem_u32(const void* p){
    unsigned a; asm("{ .reg .u64 t; cvta.to.shared.u64 t, %1; cvt.u32.u64 %0, t; }"
                    : "=r"(a) : "l"(p));
    return a;
}
__device__ __forceinline__ void ldmx4t(unsigned* r, unsigned addr){
    asm volatile("ldmatrix.sync.aligned.m8n8.x4.trans.shared.b16 {%0,%1,%2,%3}, [%4];"
        : "=r"(r[0]),"=r"(r[1]),"=r"(r[2]),"=r"(r[3]) : "r"(addr));
}
__device__ __forceinline__ void mma16816(float* d, const unsigned* a, const unsigned* b){
    asm volatile("mma.sync.aligned.m16n8k16.row.col.f32.bf16.bf16.f32 "
        "{%0,%1,%2,%3}, {%4,%5,%6,%7}, {%8,%9}, {%0,%1,%2,%3};"
        : "+f"(d[0]),"+f"(d[1]),"+f"(d[2]),"+f"(d[3])
        : "r"(a[0]),"r"(a[1]),"r"(a[2]),"r"(a[3]), "r"(b[0]),"r"(b[1]));
}
__device__ __forceinline__ unsigned pack_bf16(float x, float y){
    return (unsigned)__bfloat16_as_ushort(__float2bfloat16(x)) |
           ((unsigned)__bfloat16_as_ushort(__float2bfloat16(y)) << 16);
}

// ============ W prep: fp32 -> swizzled bf16 hi/lo tiles (B operand) ============
__global__ void prep_w(const float* __restrict__ W1, const float* __restrict__ W2){
    int idx = blockIdx.x*blockDim.x + threadIdx.x;
    if (idx >= 2*KK*CH*CH) return;
    int w   = idx / (KK*CH*CH);
    int rem = idx % (KK*CH*CH);
    int k = rem / (CH*CH);
    int i = (rem / CH) % CH;   // input channel  (GEMM K)  -> row
    int c = rem % CH;          // output channel (GEMM N)  -> col
    float v = (w ? W2 : W1)[(k*CH + i)*CH + c];
    __nv_bfloat16 h = __float2bfloat16(v);
    __nv_bfloat16 l = __float2bfloat16(v - __bfloat162float(h));
    unsigned off = i*64 + ((((unsigned)(c>>3)) ^ ((i>>1)&3)) << 4) + (c&7)*2;
    unsigned short* dst = g_wt[w] + k*2048;
    dst[off>>1]          = __bfloat16_as_ushort(h);
    dst[(off>>1) + 1024] = __bfloat16_as_ushort(l);
}

__global__ void zero_stats(){ if (threadIdx.x < 128) g_stats[threadIdx.x] = 0.f; }

// ============ pack input: fp32 row -> [hi 16w | lo 16w], permuted word order ============
// packed word q (0..15) holds channel pair p = (q>>2) + 4*(q&3), i.e. channels {2p, 2p+1}.
// Thread's 4 fragment words per row land contiguous at q = 4*(lane&3) .. +3.
// bn!=0: apply BN(stats@0, gamma, beta)+ReLU first (conv2 input h).
__global__ void pack_input(const float* __restrict__ src, unsigned* __restrict__ dst,
                           int bn, const float* __restrict__ gam, const float* __restrict__ bet)
{
    long long t = (long long)blockIdx.x*blockDim.x + threadIdx.x;
    if (t >= (long long)NP*16) return;
    int q   = (int)(t & 15);
    long long row = t >> 4;
    int p = (q >> 2) + 4*(q & 3);
    int c = 2*p;
    float2 v = *(const float2*)(src + row*CH + c);
    float x = v.x, y = v.y;
    if (bn){
        float m0 = g_stats[c]   * (1.f/NP), m1 = g_stats[c+1]   * (1.f/NP);
        float q0 = g_stats[32+c]* (1.f/NP), q1 = g_stats[32+c+1]* (1.f/NP);
        float s0 = rsqrtf(q0 - m0*m0 + 1e-5f) * gam[c];
        float s1 = rsqrtf(q1 - m1*m1 + 1e-5f) * gam[c+1];
        x = fmaxf(x*s0 + (bet[c]   - m0*s0), 0.f);
        y = fmaxf(y*s1 + (bet[c+1] - m1*s1), 0.f);
    }
    float hx = __bfloat162float(__float2bfloat16(x));
    float hy = __bfloat162float(__float2bfloat16(y));
    unsigned* o = dst + row*32;
    o[q]      = pack_bf16(x, y);
    o[16 + q] = pack_bf16(x - hx, y - hy);
}

// ============ conv via mma.sync, packed bf16 gather straight into A fragments ============
__global__ void __launch_bounds__(TPB,1) conv_mma(
    const uint4* __restrict__ pk, const unsigned short* __restrict__ wt,
    const int* __restrict__ nbr, const int* __restrict__ mask,
    float* __restrict__ out, int stats_off)
{
    extern __shared__ char smem[];
    const unsigned sb = smem_u32(smem);
    const int tid = threadIdx.x, w = tid >> 5, lane = tid & 31;
    const int tile = blockIdx.x;

    if (tid < 64) ((float*)(smem + SM_ST))[tid] = 0.f;
    // W tiles -> smem (110592B)
    {
        const uint4* s = (const uint4*)wt;
        uint4* d = (uint4*)(smem + SM_W);
        #pragma unroll 1
        for (int i = tid; i < (KK*4096)/16; i += TPB) d[i] = s[i];
    }
    // fold idx+mask -> smem, k-major I[k*IDXS + row]
    {
        long long base = (long long)tile * TILE * KK;
        int* I = (int*)(smem + SM_IDX);
        #pragma unroll 1
        for (int t = tid; t < TILE*KK; t += TPB){
            long long g = base + t;
            int vv = -1;
            if (g < (long long)NP*KK && mask[g]) vv = nbr[g];
            int row = t / KK, k = t - row*KK;
            I[k*IDXS + row] = vv;
        }
    }
    __syncthreads();

    const int RB   = w * 32;
    const int r_lo = lane >> 2;
    const int gq   = lane & 3;             // fragment word group
    const int C0   = gq * 2;
    const int* I = (const int*)(smem + SM_IDX);

    float acc[2][4][4];
    #pragma unroll
    for (int a = 0; a < 2; a++)
        #pragma unroll
        for (int b = 0; b < 4; b++)
            #pragma unroll
            for (int c = 0; c < 4; c++) acc[a][b][c] = 0.f;

    // ---- prefetch k=0 ----
    int ir[4]; uint4 vh[4], vl[4];
    #pragma unroll
    for (int m = 0; m < 4; m++) ir[m] = I[RB + r_lo + m*8];
    #pragma unroll
    for (int m = 0; m < 4; m++){
        uint4 zh = make_uint4(0,0,0,0), zl = make_uint4(0,0,0,0);
        if (ir[m] >= 0){
            const uint4* rp = pk + (size_t)ir[m]*8;
            zh = rp[gq]; zl = rp[4 + gq];
        }
        vh[m] = zh; vl[m] = zl;
    }

    #pragma unroll 2
    for (int k = 0; k < KK; k++){
        // ---- snapshot fragments (register rename under unroll) ----
        unsigned ah[2][2][4], al[2][2][4];
        #pragma unroll
        for (int rb = 0; rb < 2; rb++){
            const unsigned* r0h = (const unsigned*)&vh[2*rb];
            const unsigned* r1h = (const unsigned*)&vh[2*rb+1];
            const unsigned* r0l = (const unsigned*)&vl[2*rb];
            const unsigned* r1l = (const unsigned*)&vl[2*rb+1];
            #pragma unroll
            for (int kb = 0; kb < 2; kb++){
                ah[rb][kb][0] = r0h[2*kb];   ah[rb][kb][1] = r1h[2*kb];
                ah[rb][kb][2] = r0h[2*kb+1]; ah[rb][kb][3] = r1h[2*kb+1];
                al[rb][kb][0] = r0l[2*kb];   al[rb][kb][1] = r1l[2*kb];
                al[rb][kb][2] = r0l[2*kb+1]; al[rb][kb][3] = r1l[2*kb+1];
            }
        }

        // ---- prefetch next k ----
        if (k + 1 < KK){
            #pragma unroll
            for (int m = 0; m < 4; m++) ir[m] = I[(k+1)*IDXS + RB + r_lo + m*8];
            #pragma unroll
            for (int m = 0; m < 4; m++){
                uint4 zh = make_uint4(0,0,0,0), zl = make_uint4(0,0,0,0);
                if (ir[m] >= 0){
                    const uint4* rp = pk + (size_t)ir[m]*8;
                    zh = rp[gq]; zl = rp[4 + gq];
                }
                vh[m] = zh; vl[m] = zl;
            }
        }

        // ---- B fragments + 48 mma ----
        const unsigned wk = sb + SM_W + k*4096;
        #pragma unroll
        for (int nq = 0; nq < 4; nq++){
            unsigned bh[4], bl[4];
            unsigned sw = ((((unsigned)nq) ^ ((lane>>1)&3)) << 4);
            ldmx4t(bh, wk +        lane*64 + sw);
            ldmx4t(bl, wk + 2048 + lane*64 + sw);
            #pragma unroll
            for (int rb = 0; rb < 2; rb++){
                mma16816(acc[rb][nq], ah[rb][0], bh + 0);
                mma16816(acc[rb][nq], ah[rb][1], bh + 2);
                mma16816(acc[rb][nq], al[rb][0], bh + 0);
                mma16816(acc[rb][nq], al[rb][1], bh + 2);
                mma16816(acc[rb][nq], ah[rb][0], bl + 0);
                mma16816(acc[rb][nq], ah[rb][1], bl + 2);
            }
        }
    }

    // ---- epilogue: store raw conv output + fused BN stats ----
    float s[8], q[8];
    #pragma unroll
    for (int i = 0; i < 8; i++){ s[i] = 0.f; q[i] = 0.f; }

    const int r0 = tile*TILE + RB + r_lo;
    #pragma unroll
    for (int rb = 0; rb < 2; rb++){
        #pragma unroll
        for (int nq = 0; nq < 4; nq++){
            float a0 = acc[rb][nq][0], a1 = acc[rb][nq][1];
            float a2 = acc[rb][nq][2], a3 = acc[rb][nq][3];
            int m0 = r0 + rb*16, m1 = m0 + 8;
            int c  = nq*8 + C0;
            if (m0 < NP) *(float2*)(out + (size_t)m0*CH + c) = make_float2(a0, a1);
            if (m1 < NP) *(float2*)(out + (size_t)m1*CH + c) = make_float2(a2, a3);
            s[nq*2+0] += a0 + a2;  q[nq*2+0] += a0*a0 + a2*a2;
            s[nq*2+1] += a1 + a3;  q[nq*2+1] += a1*a1 + a3*a3;
        }
    }
    #pragma unroll
    for (int i = 0; i < 8; i++){
        #pragma unroll
        for (int off = 4; off < 32; off <<= 1){
            s[i] += __shfl_xor_sync(0xffffffffu, s[i], off);
            q[i] += __shfl_xor_sync(0xffffffffu, q[i], off);
        }
    }
    if (lane < 4){
        float* st = (float*)(smem + SM_ST);
        #pragma unroll
        for (int nq = 0; nq < 4; nq++){
            atomicAdd(&st[     nq*8 + lane*2    ], s[nq*2+0]);
            atomicAdd(&st[     nq*8 + lane*2 + 1], s[nq*2+1]);
            atomicAdd(&st[32 + nq*8 + lane*2    ], q[nq*2+0]);
            atomicAdd(&st[32 + nq*8 + lane*2 + 1], q[nq*2+1]);
        }
    }
    __syncthreads();
    if (tid < 64) atomicAdd(&g_stats[stats_off + tid], ((float*)(smem + SM_ST))[tid]);
}

// ---- final BN + residual + ReLU ----
__global__ void bnrelu_kernel(const float4* __restrict__ x, int stats_off,
    const float* __restrict__ gamma, const float* __restrict__ beta,
    const float4* __restrict__ res, float4* __restrict__ out)
{
    long long i = (long long)blockIdx.x*blockDim.x + threadIdx.x;
    if (i >= (long long)NP*CH/4) return;
    int c0 = (int)(i & 7) * 4;
    const float invN = 1.0f / NP;
    float4 v = x[i];
    float4 r4 = res[i];
    float4 o;
#define BN_ONE(comp, c) { \
        float mean = g_stats[stats_off + c0 + c] * invN; \
        float var  = g_stats[stats_off + 32 + c0 + c] * invN - mean*mean; \
        float sc   = rsqrtf(var + 1e-5f) * gamma[c0 + c]; \
        float val  = (v.comp - mean)*sc + beta[c0 + c] + r4.comp; \
        o.comp = fmaxf(val, 0.f); }
    BN_ONE(x, 0) BN_ONE(y, 1) BN_ONE(z, 2) BN_ONE(w, 3)
#undef BN_ONE
    out[i] = o;
}

extern "C" void kernel_launch(void* const* d_in, const int* in_sizes, int n_in,
                              void* d_out, int out_size)
{
    const float* feats  = (const float*)d_in[0];
    const float* W1     = (const float*)d_in[1];
    const float* gamma1 = (const float*)d_in[2];
    const float* beta1  = (const float*)d_in[3];
    const float* W2     = (const float*)d_in[4];
    const float* gamma2 = (const float*)d_in[5];
    const float* beta2  = (const float*)d_in[6];
    const int*   nbr    = (const int*)d_in[7];
    const int*   mask   = (const int*)d_in[8];
    float* out = (float*)d_out;

    float *buf1, *buf2; unsigned short* wt; unsigned* pk;
    cudaGetSymbolAddress((void**)&buf1, g_buf1);
    cudaGetSymbolAddress((void**)&buf2, g_buf2);
    cudaGetSymbolAddress((void**)&wt,   g_wt);
    cudaGetSymbolAddress((void**)&pk,   g_pk);

    cudaFuncSetAttribute(conv_mma, cudaFuncAttributeMaxDynamicSharedMemorySize, SM_TOT);

    const long long ne4 = (long long)NP*CH/4;
    const int gridb = (int)((ne4 + 255) / 256);
    const int gridp = (int)(((long long)NP*16 + 255) / 256);

    zero_stats<<<1,128>>>();
    prep_w<<<(2*KK*CH*CH + 255)/256, 256>>>(W1, W2);
    // pack feats -> pk; conv1: raw -> buf1, stats@0
    pack_input<<<gridp, 256>>>(feats, pk, 0, (const float*)0, (const float*)0);
    conv_mma<<<NT, TPB, SM_TOT>>>((const uint4*)pk, wt, nbr, mask, buf1, 0);
    // h = relu(bn1(buf1)) packed -> pk; conv2: raw -> buf2, stats@64
    pack_input<<<gridp, 256>>>(buf1, pk, 1, gamma1, beta1);
    conv_mma<<<NT, TPB, SM_TOT>>>((const uint4*)pk, wt + KK*2048, nbr, mask, buf2, 64);
    // out = relu(BN2(buf2) + feats)
    bnrelu_kernel<<<gridb, 256>>>((const float4*)buf2, 64, gamma2, beta2,
                                  (const float4*)feats, (float4*)out);
}